// round 1
// baseline (speedup 1.0000x reference)
#include <cuda_runtime.h>
#include <cstddef>

#define NA 192
#define TT 80
#define NC 5
#define JT 32
#define NTHREADS 256

__global__ __launch_bounds__(NTHREADS) void veh_coll_kernel(
    const float* __restrict__ traj,        // (NA, T, 4)
    const float* __restrict__ centroids,   // (NA, NC, 4)
    const float* __restrict__ pen,         // (NA, NA)
    float* __restrict__ out,               // [penalties (T,NA,NA)] [mask (T,NA,NA)]
    int write_mask)
{
    __shared__ float2 w[NA * NC];          // world circle centers for this t

    const int t   = blockIdx.x;
    const int j0  = blockIdx.y * JT;
    const int tid = threadIdx.x;

    // Phase 1: compute all NA*NC world circle positions for time t.
    for (int p = tid; p < NA * NC; p += NTHREADS) {
        int i = p / NC;
        int c = p - i * NC;
        const float4 tr = *reinterpret_cast<const float4*>(traj + ((size_t)i * TT + t) * 4);
        float hx = tr.z, hy = tr.w;
        float inv = rsqrtf(hx * hx + hy * hy);
        hx *= inv; hy *= inv;
        float cx = centroids[((size_t)i * NC + c) * 4 + 0];
        float cy = centroids[((size_t)i * NC + c) * 4 + 1];
        w[p] = make_float2(tr.x + hx * cx - hy * cy,
                           tr.y + hy * cx + hx * cy);
    }
    __syncthreads();

    // Phase 2: each thread owns one j (lane-indexed), loops over i.
    const int j = j0 + (tid & 31);
    float2 wj[NC];
    #pragma unroll
    for (int d = 0; d < NC; d++) wj[d] = w[j * NC + d];

    const size_t P = (size_t)TT * NA * NA;
    float* __restrict__ out_pen  = out;
    float* __restrict__ out_mask = out + P;

    for (int i = (tid >> 5); i < NA; i += NTHREADS / 32) {
        float m = 3.4e38f;
        #pragma unroll
        for (int c = 0; c < NC; c++) {
            float2 wi = w[i * NC + c];   // warp-uniform broadcast
            #pragma unroll
            for (int d = 0; d < NC; d++) {
                float dx = wi.x - wj[d].x;
                float dy = wi.y - wj[d].y;
                float d2 = fmaf(dy, dy, dx * dx);
                m = fminf(m, d2);
            }
        }
        float md = sqrtf(fmaxf(m, 0.0f));
        float pd = pen[i * NA + j];
        size_t idx = ((size_t)t * NA + i) * NA + j;
        out_pen[idx] = 1.0f - md / pd;
        if (write_mask)
            out_mask[idx] = (md <= pd && i != j) ? 1.0f : 0.0f;
    }
}

extern "C" void kernel_launch(void* const* d_in, const int* in_sizes, int n_in,
                              void* d_out, int out_size) {
    const float* traj      = (const float*)d_in[0];
    const float* centroids = (const float*)d_in[1];
    const float* pen       = (const float*)d_in[2];
    // d_in[3] = off_diag_mask (~eye) — recomputed as (i != j) on device.

    float* out = (float*)d_out;
    const size_t P = (size_t)TT * NA * NA;
    int write_mask = ((size_t)out_size >= 2 * P) ? 1 : 0;

    dim3 grid(TT, NA / JT);   // (80, 6)
    veh_coll_kernel<<<grid, NTHREADS>>>(traj, centroids, pen, out, write_mask);
}

// round 2
// speedup vs baseline: 1.2750x; 1.2750x over previous
#include <cuda_runtime.h>
#include <cstddef>

#define NA 192
#define TT 80
#define NC 5
#define TILE 32
#define NTHREADS 256
#define NTILES (NA / TILE)   // 6

struct Agent {
    float4 pose;        // px, py, hx, hy (normalized)
    float4 circ[NC];    // s, s^2, 2s, 0
};

__global__ __launch_bounds__(NTHREADS) void veh_coll_kernel(
    const float* __restrict__ traj,        // (NA, T, 4)
    const float* __restrict__ centroids,   // (NA, NC, 4)
    const float* __restrict__ pen,         // (NA, NA)
    float* __restrict__ out,               // [pen (T,NA,NA)][mask (T,NA,NA)]
    int write_mask)
{
    __shared__ Agent sI[TILE];
    __shared__ Agent sJ[TILE];

    const int t   = blockIdx.x;
    const int jt  = blockIdx.y;
    const int it  = blockIdx.z;
    const int tid = threadIdx.x;

    // ---- Phase 1: stage agent data for the i-tile and j-tile ----
    for (int p = tid; p < 2 * TILE; p += NTHREADS) {
        int side = p >> 5;              // 0 = I side, 1 = J side
        int loc  = p & 31;
        int a    = (side ? jt : it) * TILE + loc;
        float4 tr = *reinterpret_cast<const float4*>(traj + ((size_t)a * TT + t) * 4);
        float inv = rsqrtf(tr.z * tr.z + tr.w * tr.w);
        float4 pose = make_float4(tr.x, tr.y, tr.z * inv, tr.w * inv);
        if (side) sJ[loc].pose = pose; else sI[loc].pose = pose;
    }
    for (int p = tid; p < 2 * TILE * NC; p += NTHREADS) {
        int side = p / (TILE * NC);
        int r    = p - side * (TILE * NC);
        int loc  = r / NC;
        int c    = r - loc * NC;
        int a    = (side ? jt : it) * TILE + loc;
        float sc = centroids[((size_t)a * NC + c) * 4];
        float4 v = make_float4(sc, sc * sc, 2.0f * sc, 0.0f);
        if (side) sJ[loc].circ[c] = v; else sI[loc].circ[c] = v;
    }
    __syncthreads();

    // ---- Phase 2: lane = j within tile; each warp covers 4 i's ----
    const int jl   = tid & 31;
    const int warp = tid >> 5;
    const int jg   = jt * TILE + jl;

    const float4 pj = sJ[jl].pose;
    float sj[NC], s2j[NC], twj[NC];
    #pragma unroll
    for (int d = 0; d < NC; d++) {
        float4 cj = sJ[jl].circ[d];
        sj[d] = cj.x; s2j[d] = cj.y; twj[d] = cj.z;
    }

    const size_t P = (size_t)TT * NA * NA;

    #pragma unroll
    for (int w = 0; w < TILE / (NTHREADS / 32); ++w) {
        const int il = warp + w * (NTHREADS / 32);
        const int ig = it * TILE + il;

        const float4 pi = sI[il].pose;
        float dx = pi.x - pj.x;
        float dy = pi.y - pj.y;
        float a  = fmaf(dy, pi.w, dx * pi.z);   // base . h_i
        float b  = fmaf(dy, pj.w, dx * pj.z);   // base . h_j
        float g  = fmaf(pi.w, pj.w, pi.z * pj.z); // h_i . h_j
        float B  = fmaf(dy, dy, dx * dx);
        float g2 = g + g;

        float v[NC];
        #pragma unroll
        for (int d = 0; d < NC; d++)
            v[d] = fmaf(-b, twj[d], s2j[d]) + B;

        float m = 3.4e38f;
        #pragma unroll
        for (int c = 0; c < NC; c++) {
            float4 ci = sI[il].circ[c];         // broadcast LDS.128
            float u = fmaf(ci.z, a, ci.y);      // s_c^2 + 2 a s_c
            float k = g2 * ci.x;                // 2 g s_c
            float mc = fmaf(-k, sj[0], v[0]);
            #pragma unroll
            for (int d = 1; d < NC; d++)
                mc = fminf(mc, fmaf(-k, sj[d], v[d]));
            m = fminf(m, mc + u);
        }

        float md = sqrtf(fmaxf(m, 0.0f));
        float pd = pen[ig * NA + jg];
        size_t idx = ((size_t)t * NA + ig) * NA + jg;
        out[idx] = 1.0f - __fdividef(md, pd);
        if (write_mask)
            out[P + idx] = (md <= pd && ig != jg) ? 1.0f : 0.0f;
    }
}

extern "C" void kernel_launch(void* const* d_in, const int* in_sizes, int n_in,
                              void* d_out, int out_size) {
    const float* traj      = (const float*)d_in[0];
    const float* centroids = (const float*)d_in[1];
    const float* pen       = (const float*)d_in[2];
    // d_in[3] = off_diag_mask (~eye) — recomputed as (i != j) on device.

    float* out = (float*)d_out;
    const size_t P = (size_t)TT * NA * NA;
    int write_mask = ((size_t)out_size >= 2 * P) ? 1 : 0;

    dim3 grid(TT, NTILES, NTILES);   // (80, 6, 6) = 2880 blocks
    veh_coll_kernel<<<grid, NTHREADS>>>(traj, centroids, pen, out, write_mask);
}

// round 3
// speedup vs baseline: 1.8142x; 1.4229x over previous
#include <cuda_runtime.h>
#include <cstddef>

#define NA 192
#define TT 80
#define NC 5
#define TILE 32
#define NTHREADS 256
#define NPAIRS 21

__constant__ unsigned char cIT[NPAIRS] = {0,0,0,0,0,0,1,1,1,1,1,2,2,2,2,3,3,3,4,4,5};
__constant__ unsigned char cJT[NPAIRS] = {0,1,2,3,4,5,1,2,3,4,5,2,3,4,5,3,4,5,4,5,5};

__global__ __launch_bounds__(NTHREADS) void veh_coll_kernel(
    const float* __restrict__ traj,        // (NA, T, 4)
    const float* __restrict__ centroids,   // (NA, NC, 4)
    const float* __restrict__ pen,         // (NA, NA)
    float* __restrict__ out,               // [pen (T,NA,NA)][mask (T,NA,NA)]
    int write_mask)
{
    __shared__ float4 sPose[2 * TILE];        // i-tile in [0,32), j-tile in [32,64)
    __shared__ float4 sS4[2 * TILE][2];       // s0..s3, s4 (padded)
    __shared__ float  sTile[TILE][TILE + 1];  // penalty values for transpose

    const int t   = blockIdx.x;
    const int pr  = blockIdx.y;
    const int it  = cIT[pr];
    const int jt  = cJT[pr];
    const int tid = threadIdx.x;

    // ---- Stage poses (normalize heading) ----
    if (tid < 2 * TILE) {
        int side = tid >> 5, loc = tid & 31;
        int a = (side ? jt : it) * TILE + loc;
        float4 tr = *reinterpret_cast<const float4*>(traj + ((size_t)a * TT + t) * 4);
        float inv = rsqrtf(tr.z * tr.z + tr.w * tr.w);
        sPose[tid] = make_float4(tr.x, tr.y, tr.z * inv, tr.w * inv);
    }
    // ---- Stage s values (centroid x-offsets; cy == 0 by construction) ----
    for (int p = tid; p < 2 * TILE * NC; p += NTHREADS) {
        int q = p / NC;                // agent slot 0..63
        int c = p - q * NC;
        int side = q >> 5, loc = q & 31;
        int a = (side ? jt : it) * TILE + loc;
        reinterpret_cast<float*>(&sS4[q][0])[c] = centroids[((size_t)a * NC + c) * 4];
    }
    __syncthreads();

    // ---- Compute: lane = j local, each warp covers 4 i's ----
    const int jl   = tid & 31;
    const int warp = tid >> 5;
    const int jg   = jt * TILE + jl;

    const float4 pj = sPose[TILE + jl];
    float sjv[NC];
    {
        float4 a0 = sS4[TILE + jl][0];
        sjv[0] = a0.x; sjv[1] = a0.y; sjv[2] = a0.z; sjv[3] = a0.w;
        sjv[4] = sS4[TILE + jl][1].x;
    }

    const size_t P = (size_t)TT * NA * NA;

    #pragma unroll
    for (int w = 0; w < TILE / (NTHREADS / 32); ++w) {
        const int il = warp + w * (NTHREADS / 32);
        const int ig = it * TILE + il;

        const float4 pi = sPose[il];
        float4 sa = sS4[il][0];
        float si0 = sa.x, si1 = sa.y, si2 = sa.z, si3 = sa.w;
        float si4 = sS4[il][1].x;

        float dx = pi.x - pj.x;
        float dy = pi.y - pj.y;
        float a  = fmaf(dy, pi.w, dx * pi.z);       // base . h_i
        float b  = fmaf(dy, pj.w, dx * pj.z);       // base . h_j
        float g  = fmaf(pi.w, pj.w, pi.z * pj.z);   // h_i . h_j
        float B  = fmaf(dy, dy, dx * dx);
        float a2 = a + a, b2 = b + b, g2 = g + g;

        float v[NC];
        #pragma unroll
        for (int d = 0; d < NC; d++)
            v[d] = fmaf(sjv[d], sjv[d] - b2, B);    // B + s_d^2 - 2 b s_d

        float si[NC] = {si0, si1, si2, si3, si4};
        float m = 3.4e38f;
        #pragma unroll
        for (int c = 0; c < NC; c++) {
            float u = si[c] * (si[c] + a2);          // s_c^2 + 2 a s_c
            float k = g2 * si[c];                    // 2 g s_c
            float mc = fmaf(-k, sjv[0], v[0]);
            #pragma unroll
            for (int d = 1; d < NC; d++)
                mc = fminf(mc, fmaf(-k, sjv[d], v[d]));
            m = fminf(m, mc + u);
        }

        float md = sqrtf(fmaxf(m, 0.0f));
        float pd = pen[ig * NA + jg];
        float pv = 1.0f - __fdividef(md, pd);
        size_t idx = ((size_t)t * NA + ig) * NA + jg;
        out[idx] = pv;
        if (write_mask)
            out[P + idx] = (pv >= 0.0f && ig != jg) ? 1.0f : 0.0f;
        sTile[il][jl] = pv;
    }

    // ---- Transposed write for off-diagonal tile pairs ----
    if (it != jt) {
        __syncthreads();
        #pragma unroll
        for (int q = 0; q < (TILE * TILE) / NTHREADS; ++q) {
            int e  = tid + q * NTHREADS;
            int jj = e >> 5;
            int ii = e & 31;
            float pv = sTile[ii][jj];                // stride-33 read: conflict-free
            size_t idx = ((size_t)t * NA + jt * TILE + jj) * NA + it * TILE + ii;
            out[idx] = pv;
            if (write_mask)
                out[P + idx] = (pv >= 0.0f) ? 1.0f : 0.0f;  // it!=jt -> never diagonal
        }
    }
}

extern "C" void kernel_launch(void* const* d_in, const int* in_sizes, int n_in,
                              void* d_out, int out_size) {
    const float* traj      = (const float*)d_in[0];
    const float* centroids = (const float*)d_in[1];
    const float* pen       = (const float*)d_in[2];
    // d_in[3] = off_diag_mask (~eye) — recomputed as (i != j) on device.

    float* out = (float*)d_out;
    const size_t P = (size_t)TT * NA * NA;
    int write_mask = ((size_t)out_size >= 2 * P) ? 1 : 0;

    dim3 grid(TT, NPAIRS);   // (80, 21) = 1680 blocks
    veh_coll_kernel<<<grid, NTHREADS>>>(traj, centroids, pen, out, write_mask);
}